// round 4
// baseline (speedup 1.0000x reference)
#include <cuda_runtime.h>
#include <cstdint>

#define NMAX 1000000
#define EMAX 16000000
#define SCAN_CHUNK 1024  // elements per scan block (256 thr * 4)

// Scratch (__device__ globals; no allocation allowed)
__device__ float4 g_projA[NMAX];       // layer-1 projd (with dinv folded)
__device__ float4 g_projB[NMAX];       // layer-2 projd
__device__ float2 g_p2[NMAX];          // layer-3 projd
__device__ float  g_dinv[NMAX];        // rsqrt(deg)
__device__ int    g_cursor[NMAX];      // degree -> start cursor (mutated by build)
__device__ int    g_starts[NMAX + 1];  // CSR row starts (by target)
__device__ int    g_csr[EMAX];         // CSR source indices
__device__ int    g_blockSums[1024];
__device__ int    g_blockOffs[1024];

// ---------------------------------------------------------------------------
// zero cursor
// ---------------------------------------------------------------------------
__global__ void k_zero(int n) {
    int i = blockIdx.x * blockDim.x + threadIdx.x;
    if (i < n) g_cursor[i] = 0;
}

// ---------------------------------------------------------------------------
// int degree histogram over targets (no return -> RED)
// ---------------------------------------------------------------------------
__device__ __forceinline__ void red_cnt(int c) {
    int one = 1;
    asm volatile("red.global.add.u32 [%0], %1;" :: "l"(&g_cursor[c]), "r"(one) : "memory");
}

__global__ void k_count(const int* __restrict__ col, int E) {
    int t = blockIdx.x * blockDim.x + threadIdx.x;
    int base = t * 8;
    if (base + 8 <= E) {
        int4 c0 = __ldcs(reinterpret_cast<const int4*>(col + base));
        int4 c1 = __ldcs(reinterpret_cast<const int4*>(col + base) + 1);
        red_cnt(c0.x); red_cnt(c0.y); red_cnt(c0.z); red_cnt(c0.w);
        red_cnt(c1.x); red_cnt(c1.y); red_cnt(c1.z); red_cnt(c1.w);
    } else if (base < E) {
        for (int j = base; j < E; j++) red_cnt(__ldcs(col + j));
    }
}

// ---------------------------------------------------------------------------
// scan stage 1: per-block totals of g_cursor
// ---------------------------------------------------------------------------
__global__ void k_scan_blocks(int n) {
    int b = blockIdx.x, t = threadIdx.x;
    int base = b * SCAN_CHUNK + t * 4;
    int s = 0;
    if (base + 3 < n) {
        int4 v = *reinterpret_cast<const int4*>(&g_cursor[base]);
        s = v.x + v.y + v.z + v.w;
    } else {
        for (int j = 0; j < 4; j++) if (base + j < n) s += g_cursor[base + j];
    }
    #pragma unroll
    for (int o = 16; o; o >>= 1) s += __shfl_down_sync(0xffffffffu, s, o);
    __shared__ int ws[8];
    if ((t & 31) == 0) ws[t >> 5] = s;
    __syncthreads();
    if (t < 8) {
        int v = ws[t];
        #pragma unroll
        for (int o = 4; o; o >>= 1) v += __shfl_down_sync(0xffu, v, o);
        if (t == 0) g_blockSums[b] = v;
    }
}

// ---------------------------------------------------------------------------
// scan stage 2: exclusive scan of block totals (single 1024-thread block)
// ---------------------------------------------------------------------------
__global__ void k_scan_top(int nb, int n, int E) {
    __shared__ int sm[1024];
    int t = threadIdx.x;
    int orig = (t < nb) ? g_blockSums[t] : 0;
    sm[t] = orig;
    __syncthreads();
    for (int o = 1; o < 1024; o <<= 1) {
        int v = (t >= o) ? sm[t - o] : 0;
        __syncthreads();
        sm[t] += v;
        __syncthreads();
    }
    if (t < nb) g_blockOffs[t] = sm[t] - orig;   // exclusive
    if (t == 0) g_starts[n] = E;
}

// ---------------------------------------------------------------------------
// scan stage 3: in-block exclusive scan + offset.
// Writes starts, resets cursor to starts, computes dinv = rsqrt(deg+1).
// ---------------------------------------------------------------------------
__global__ void k_scan_apply(int n) {
    int b = blockIdx.x, t = threadIdx.x;
    int base = b * SCAN_CHUNK + t * 4;

    int4 v = make_int4(0, 0, 0, 0);
    if (base + 3 < n) {
        v = *reinterpret_cast<const int4*>(&g_cursor[base]);
    } else {
        if (base + 0 < n) v.x = g_cursor[base + 0];
        if (base + 1 < n) v.y = g_cursor[base + 1];
        if (base + 2 < n) v.z = g_cursor[base + 2];
        if (base + 3 < n) v.w = g_cursor[base + 3];
    }
    int s = v.x + v.y + v.z + v.w;

    // inclusive warp scan of thread sums
    int lane = t & 31;
    int sc = s;
    #pragma unroll
    for (int o = 1; o < 32; o <<= 1) {
        int u = __shfl_up_sync(0xffffffffu, sc, o);
        if (lane >= o) sc += u;
    }
    __shared__ int ws[8], wo[8];
    if (lane == 31) ws[t >> 5] = sc;
    __syncthreads();
    if (t < 8) {
        int u = ws[t];
        int acc = u;
        #pragma unroll
        for (int o = 1; o < 8; o <<= 1) {
            int q = __shfl_up_sync(0xffu, acc, o);
            if (t >= o) acc += q;
        }
        wo[t] = acc - u;  // exclusive warp offset
    }
    __syncthreads();

    int excl = (sc - s) + wo[t >> 5] + g_blockOffs[b];
    int p0 = excl, p1 = p0 + v.x, p2 = p1 + v.y, p3 = p2 + v.z;

    if (base + 3 < n) {
        *reinterpret_cast<int4*>(&g_starts[base]) = make_int4(p0, p1, p2, p3);
        *reinterpret_cast<int4*>(&g_cursor[base]) = make_int4(p0, p1, p2, p3);
        *reinterpret_cast<float4*>(&g_dinv[base]) =
            make_float4(rsqrtf((float)v.x + 1.f), rsqrtf((float)v.y + 1.f),
                        rsqrtf((float)v.z + 1.f), rsqrtf((float)v.w + 1.f));
    } else {
        int ps[4] = {p0, p1, p2, p3};
        int ds[4] = {v.x, v.y, v.z, v.w};
        for (int j = 0; j < 4; j++) {
            if (base + j < n) {
                g_starts[base + j] = ps[j];
                g_cursor[base + j] = ps[j];
                g_dinv[base + j] = rsqrtf((float)ds[j] + 1.f);
            }
        }
    }
}

// ---------------------------------------------------------------------------
// Fused: CSR build (blocks [0, BB)) || layer-1 projection (blocks [BB, grid)).
// proj: projd = (x @ W1) * dinv via 2-node warp transpose reduction.
// ---------------------------------------------------------------------------
__global__ void k_build_proj1(const float* __restrict__ x,
                              const float* __restrict__ W1,
                              const int* __restrict__ row,
                              const int* __restrict__ col,
                              int n, int E, int buildBlocks) {
    if ((int)blockIdx.x < buildBlocks) {
        // ---- CSR build ----
        int t = blockIdx.x * blockDim.x + threadIdx.x;
        int nthreads = buildBlocks * blockDim.x;
        int nchunks = E >> 3;
        for (int ch = t; ch < nchunks; ch += nthreads) {
            int base = ch * 8;
            int4 r0 = __ldcs(reinterpret_cast<const int4*>(row + base));
            int4 r1 = __ldcs(reinterpret_cast<const int4*>(row + base) + 1);
            int4 c0 = __ldcs(reinterpret_cast<const int4*>(col + base));
            int4 c1 = __ldcs(reinterpret_cast<const int4*>(col + base) + 1);
            __stcg(&g_csr[atomicAdd(&g_cursor[c0.x], 1)], r0.x);
            __stcg(&g_csr[atomicAdd(&g_cursor[c0.y], 1)], r0.y);
            __stcg(&g_csr[atomicAdd(&g_cursor[c0.z], 1)], r0.z);
            __stcg(&g_csr[atomicAdd(&g_cursor[c0.w], 1)], r0.w);
            __stcg(&g_csr[atomicAdd(&g_cursor[c1.x], 1)], r1.x);
            __stcg(&g_csr[atomicAdd(&g_cursor[c1.y], 1)], r1.y);
            __stcg(&g_csr[atomicAdd(&g_cursor[c1.z], 1)], r1.z);
            __stcg(&g_csr[atomicAdd(&g_cursor[c1.w], 1)], r1.w);
        }
        int rem = E - nchunks * 8;
        if (t < rem) {
            int j = nchunks * 8 + t;
            int c = __ldcs(col + j);
            int r = __ldcs(row + j);
            __stcg(&g_csr[atomicAdd(&g_cursor[c], 1)], r);
        }
        return;
    }

    // ---- layer-1 projection ----
    int lane = threadIdx.x & 31;
    int warp = ((blockIdx.x - buildBlocks) * blockDim.x + threadIdx.x) >> 5;
    int nwarps = ((gridDim.x - buildBlocks) * blockDim.x) >> 5;

    const float4* W = reinterpret_cast<const float4*>(W1);
    float4 w0 = W[4 * lane + 0];
    float4 w1 = W[4 * lane + 1];
    float4 w2 = W[4 * lane + 2];
    float4 w3 = W[4 * lane + 3];

    const float4* x4 = reinterpret_cast<const float4*>(x);
    const unsigned FULL = 0xffffffffu;
    int npairs = (n + 1) >> 1;

    for (int pair = warp; pair < npairs; pair += nwarps) {
        int nodeA = pair * 2;
        int nodeB = nodeA + 1;
        bool hasB = nodeB < n;

        float4 xa = __ldcs(x4 + (size_t)nodeA * 32 + lane);
        float4 xb = hasB ? __ldcs(x4 + (size_t)nodeB * 32 + lane)
                         : make_float4(0.f, 0.f, 0.f, 0.f);

        float a0 = xa.x * w0.x + xa.y * w1.x + xa.z * w2.x + xa.w * w3.x;
        float a1 = xa.x * w0.y + xa.y * w1.y + xa.z * w2.y + xa.w * w3.y;
        float a2 = xa.x * w0.z + xa.y * w1.z + xa.z * w2.z + xa.w * w3.z;
        float a3 = xa.x * w0.w + xa.y * w1.w + xa.z * w2.w + xa.w * w3.w;
        float b0 = xb.x * w0.x + xb.y * w1.x + xb.z * w2.x + xb.w * w3.x;
        float b1 = xb.x * w0.y + xb.y * w1.y + xb.z * w2.y + xb.w * w3.y;
        float b2 = xb.x * w0.z + xb.y * w1.z + xb.z * w2.z + xb.w * w3.z;
        float b3 = xb.x * w0.w + xb.y * w1.w + xb.z * w2.w + xb.w * w3.w;

        a0 += __shfl_xor_sync(FULL, a0, 16); b0 += __shfl_xor_sync(FULL, b0, 16);
        a1 += __shfl_xor_sync(FULL, a1, 16); b1 += __shfl_xor_sync(FULL, b1, 16);
        a2 += __shfl_xor_sync(FULL, a2, 16); b2 += __shfl_xor_sync(FULL, b2, 16);
        a3 += __shfl_xor_sync(FULL, a3, 16); b3 += __shfl_xor_sync(FULL, b3, 16);
        a0 += __shfl_xor_sync(FULL, a0, 8);  b0 += __shfl_xor_sync(FULL, b0, 8);
        a1 += __shfl_xor_sync(FULL, a1, 8);  b1 += __shfl_xor_sync(FULL, b1, 8);
        a2 += __shfl_xor_sync(FULL, a2, 8);  b2 += __shfl_xor_sync(FULL, b2, 8);
        a3 += __shfl_xor_sync(FULL, a3, 8);  b3 += __shfl_xor_sync(FULL, b3, 8);

        int g = lane >> 3;
        float va = (g == 0) ? a0 : (g == 1) ? a1 : (g == 2) ? a2 : a3;
        float vb = (g == 0) ? b0 : (g == 1) ? b1 : (g == 2) ? b2 : b3;
        va += __shfl_xor_sync(FULL, va, 4);  vb += __shfl_xor_sync(FULL, vb, 4);
        va += __shfl_xor_sync(FULL, va, 2);  vb += __shfl_xor_sync(FULL, vb, 2);
        va += __shfl_xor_sync(FULL, va, 1);  vb += __shfl_xor_sync(FULL, vb, 1);

        int sub = lane & 7;
        bool isA = (sub == 0);
        bool isB = (sub == 4) && hasB;
        if (isA | isB) {
            int nod = isA ? nodeA : nodeB;
            float v = isA ? va : vb;
            float d = __ldg(&g_dinv[nod]);
            reinterpret_cast<float*>(&g_projA[nod])[g] = v * d;
        }
    }
}

// ---------------------------------------------------------------------------
// Gather layer 1 -> projd2:  s = projA[i] + sum_r projA[r];
// t = tanh(s*dinv + b1); projB = (t @ W2) * dinv.
// ---------------------------------------------------------------------------
__global__ void k_gather12(const float* __restrict__ W2,
                           const float* __restrict__ b1, int n) {
    int i = blockIdx.x * blockDim.x + threadIdx.x;
    if (i >= n) return;
    float4 s = g_projA[i];
    int st = g_starts[i], en = g_starts[i + 1];
    int k = st;
    for (; k + 4 <= en; k += 4) {
        int r0 = __ldcs(&g_csr[k + 0]);
        int r1 = __ldcs(&g_csr[k + 1]);
        int r2 = __ldcs(&g_csr[k + 2]);
        int r3 = __ldcs(&g_csr[k + 3]);
        float4 p0 = __ldcg(&g_projA[r0]);
        float4 p1 = __ldcg(&g_projA[r1]);
        float4 p2 = __ldcg(&g_projA[r2]);
        float4 p3 = __ldcg(&g_projA[r3]);
        s.x += p0.x + p1.x + p2.x + p3.x;
        s.y += p0.y + p1.y + p2.y + p3.y;
        s.z += p0.z + p1.z + p2.z + p3.z;
        s.w += p0.w + p1.w + p2.w + p3.w;
    }
    for (; k < en; k++) {
        float4 p = __ldcg(&g_projA[__ldcs(&g_csr[k])]);
        s.x += p.x; s.y += p.y; s.z += p.z; s.w += p.w;
    }
    float d = g_dinv[i];
    float t0 = tanhf(s.x * d + __ldg(&b1[0]));
    float t1 = tanhf(s.y * d + __ldg(&b1[1]));
    float t2 = tanhf(s.z * d + __ldg(&b1[2]));
    float t3 = tanhf(s.w * d + __ldg(&b1[3]));
    float4 p;
    p.x = (t0 * __ldg(&W2[0]) + t1 * __ldg(&W2[4]) + t2 * __ldg(&W2[8])  + t3 * __ldg(&W2[12])) * d;
    p.y = (t0 * __ldg(&W2[1]) + t1 * __ldg(&W2[5]) + t2 * __ldg(&W2[9])  + t3 * __ldg(&W2[13])) * d;
    p.z = (t0 * __ldg(&W2[2]) + t1 * __ldg(&W2[6]) + t2 * __ldg(&W2[10]) + t3 * __ldg(&W2[14])) * d;
    p.w = (t0 * __ldg(&W2[3]) + t1 * __ldg(&W2[7]) + t2 * __ldg(&W2[11]) + t3 * __ldg(&W2[15])) * d;
    g_projB[i] = p;
}

// ---------------------------------------------------------------------------
// Gather layer 2 -> projd3 (2-wide out)
// ---------------------------------------------------------------------------
__global__ void k_gather23(const float* __restrict__ W3,
                           const float* __restrict__ b2, int n) {
    int i = blockIdx.x * blockDim.x + threadIdx.x;
    if (i >= n) return;
    float4 s = g_projB[i];
    int st = g_starts[i], en = g_starts[i + 1];
    int k = st;
    for (; k + 4 <= en; k += 4) {
        int r0 = __ldcs(&g_csr[k + 0]);
        int r1 = __ldcs(&g_csr[k + 1]);
        int r2 = __ldcs(&g_csr[k + 2]);
        int r3 = __ldcs(&g_csr[k + 3]);
        float4 p0 = __ldcg(&g_projB[r0]);
        float4 p1 = __ldcg(&g_projB[r1]);
        float4 p2 = __ldcg(&g_projB[r2]);
        float4 p3 = __ldcg(&g_projB[r3]);
        s.x += p0.x + p1.x + p2.x + p3.x;
        s.y += p0.y + p1.y + p2.y + p3.y;
        s.z += p0.z + p1.z + p2.z + p3.z;
        s.w += p0.w + p1.w + p2.w + p3.w;
    }
    for (; k < en; k++) {
        float4 p = __ldcg(&g_projB[__ldcs(&g_csr[k])]);
        s.x += p.x; s.y += p.y; s.z += p.z; s.w += p.w;
    }
    float d = g_dinv[i];
    float t0 = tanhf(s.x * d + __ldg(&b2[0]));
    float t1 = tanhf(s.y * d + __ldg(&b2[1]));
    float t2 = tanhf(s.z * d + __ldg(&b2[2]));
    float t3 = tanhf(s.w * d + __ldg(&b2[3]));
    float p0 = (t0 * __ldg(&W3[0]) + t1 * __ldg(&W3[2]) + t2 * __ldg(&W3[4]) + t3 * __ldg(&W3[6])) * d;
    float p1 = (t0 * __ldg(&W3[1]) + t1 * __ldg(&W3[3]) + t2 * __ldg(&W3[5]) + t3 * __ldg(&W3[7])) * d;
    g_p2[i] = make_float2(p0, p1);
}

// ---------------------------------------------------------------------------
// Gather layer 3 + epilogue: h = tanh(s*dinv + b3); out = h @ Wc + bc.
// d_out: out[N,16] then h[N,2]; coalesced out writes via smem staging.
// ---------------------------------------------------------------------------
__global__ void k_gather3f(const float* __restrict__ Wc,
                           const float* __restrict__ b3,
                           const float* __restrict__ bc,
                           float* __restrict__ out, int n) {
    __shared__ float sh0[256];
    __shared__ float sh1[256];
    int node = blockIdx.x * 256 + threadIdx.x;
    float h0 = 0.f, h1 = 0.f;
    if (node < n) {
        float2 s = g_p2[node];
        int st = g_starts[node], en = g_starts[node + 1];
        int k = st;
        for (; k + 4 <= en; k += 4) {
            int r0 = __ldcs(&g_csr[k + 0]);
            int r1 = __ldcs(&g_csr[k + 1]);
            int r2 = __ldcs(&g_csr[k + 2]);
            int r3 = __ldcs(&g_csr[k + 3]);
            float2 p0 = __ldcg(&g_p2[r0]);
            float2 p1 = __ldcg(&g_p2[r1]);
            float2 p2 = __ldcg(&g_p2[r2]);
            float2 p3 = __ldcg(&g_p2[r3]);
            s.x += p0.x + p1.x + p2.x + p3.x;
            s.y += p0.y + p1.y + p2.y + p3.y;
        }
        for (; k < en; k++) {
            float2 p = __ldcg(&g_p2[__ldcs(&g_csr[k])]);
            s.x += p.x; s.y += p.y;
        }
        float d = g_dinv[node];
        h0 = tanhf(s.x * d + __ldg(&b3[0]));
        h1 = tanhf(s.y * d + __ldg(&b3[1]));
        float2* hp = reinterpret_cast<float2*>(out + (size_t)16 * n);
        __stcs(hp + node, make_float2(h0, h1));
    }
    sh0[threadIdx.x] = h0;
    sh1[threadIdx.x] = h1;
    __syncthreads();

    int blockNodes = min(256, n - (int)blockIdx.x * 256);
    if (blockNodes <= 0) return;
    float4* o4 = reinterpret_cast<float4*>(out + (size_t)blockIdx.x * 256 * 16);
    for (int idx = threadIdx.x; idx < blockNodes * 4; idx += 256) {
        int nd = idx >> 2;
        int j  = (idx & 3) * 4;
        float H0 = sh0[nd], H1 = sh1[nd];
        float4 v;
        v.x = H0 * __ldg(&Wc[j + 0]) + H1 * __ldg(&Wc[16 + j + 0]) + __ldg(&bc[j + 0]);
        v.y = H0 * __ldg(&Wc[j + 1]) + H1 * __ldg(&Wc[16 + j + 1]) + __ldg(&bc[j + 1]);
        v.z = H0 * __ldg(&Wc[j + 2]) + H1 * __ldg(&Wc[16 + j + 2]) + __ldg(&bc[j + 2]);
        v.w = H0 * __ldg(&Wc[j + 3]) + H1 * __ldg(&Wc[16 + j + 3]) + __ldg(&bc[j + 3]);
        __stcs(o4 + idx, v);
    }
}

// ---------------------------------------------------------------------------
// Launch
// ---------------------------------------------------------------------------
extern "C" void kernel_launch(void* const* d_in, const int* in_sizes, int n_in,
                              void* d_out, int out_size) {
    const float* x  = (const float*)d_in[0];
    const int*   ei = (const int*)d_in[1];
    const float* W1 = (const float*)d_in[2];
    const float* b1 = (const float*)d_in[3];
    const float* W2 = (const float*)d_in[4];
    const float* b2 = (const float*)d_in[5];
    const float* W3 = (const float*)d_in[6];
    const float* b3 = (const float*)d_in[7];
    const float* Wc = (const float*)d_in[8];
    const float* bc = (const float*)d_in[9];
    float* out = (float*)d_out;

    const int n = in_sizes[0] / 128;
    const int E = in_sizes[1] / 2;
    const int* row = ei;       // source
    const int* col = ei + E;   // target

    const int TB = 256;
    int nodeBlocks = (n + TB - 1) / TB;
    int edgeBlocks = ((E + 7) / 8 + TB - 1) / TB;
    int scanBlocks = (n + SCAN_CHUNK - 1) / SCAN_CHUNK;

    const int BUILD_BLOCKS = 148 * 4;
    const int PROJ_BLOCKS  = 148 * 4;

    // CSR prep
    k_zero<<<nodeBlocks, TB>>>(n);
    k_count<<<edgeBlocks, TB>>>(col, E);
    k_scan_blocks<<<scanBlocks, TB>>>(n);
    k_scan_top<<<1, 1024>>>(scanBlocks, n, E);
    k_scan_apply<<<scanBlocks, TB>>>(n);

    // build CSR || layer-1 projection (block-specialized fusion)
    k_build_proj1<<<BUILD_BLOCKS + PROJ_BLOCKS, TB>>>(x, W1, row, col, n, E, BUILD_BLOCKS);

    // pull-mode layers (fused node transforms)
    k_gather12<<<nodeBlocks, TB>>>(W2, b1, n);
    k_gather23<<<nodeBlocks, TB>>>(W3, b2, n);
    k_gather3f<<<nodeBlocks, TB>>>(Wc, b3, bc, out, n);
}

// round 5
// speedup vs baseline: 1.4449x; 1.4449x over previous
#include <cuda_runtime.h>
#include <cstdint>

#define NMAX 1000000

// Scratch (__device__ globals; no allocation allowed)
__device__ float4   g_proj[NMAX];   // projd (layers 1,2) ; layer1 raw before seed
__device__ float4   g_agg[NMAX];    // running sum (seeded with projd[self])
__device__ float    g_dinv[NMAX];   // rsqrt(deg)
__device__ unsigned g_deg[NMAX];    // integer degree
__device__ float2   g_p2[NMAX];     // layer-3 projd (2-wide)
__device__ float2   g_a2[NMAX];     // layer-3 sum

// ---------------------------------------------------------------------------
// init degree = 1 (self-loop)
// ---------------------------------------------------------------------------
__global__ void k_init_deg(int n) {
    int i = blockIdx.x * blockDim.x + threadIdx.x;
    if (i < n) g_deg[i] = 1u;
}

// ---------------------------------------------------------------------------
// Fused: degree count (blocks [0,CB)) || layer-1 raw projection (rest).
// proj: raw = x @ W1 via 2-node warp transpose reduction (no dinv yet).
// ---------------------------------------------------------------------------
__device__ __forceinline__ void red_cnt(int c) {
    unsigned one = 1u;
    asm volatile("red.global.add.u32 [%0], %1;" :: "l"(&g_deg[c]), "r"(one) : "memory");
}

__global__ void __launch_bounds__(256, 6)
k_count_proj1(const float* __restrict__ x, const float* __restrict__ W1,
              const int* __restrict__ col, int n, int E, int countBlocks) {
    if ((int)blockIdx.x < countBlocks) {
        // ---- degree histogram ----
        int t = blockIdx.x * blockDim.x + threadIdx.x;
        int nthreads = countBlocks * blockDim.x;
        int nchunks = E >> 3;
        for (int ch = t; ch < nchunks; ch += nthreads) {
            int base = ch * 8;
            int4 c0 = __ldcs(reinterpret_cast<const int4*>(col + base));
            int4 c1 = __ldcs(reinterpret_cast<const int4*>(col + base) + 1);
            red_cnt(c0.x); red_cnt(c0.y); red_cnt(c0.z); red_cnt(c0.w);
            red_cnt(c1.x); red_cnt(c1.y); red_cnt(c1.z); red_cnt(c1.w);
        }
        int rem = E - nchunks * 8;
        if (t < rem) red_cnt(__ldcs(col + nchunks * 8 + t));
        return;
    }

    // ---- layer-1 raw projection ----
    int lane = threadIdx.x & 31;
    int warp = ((blockIdx.x - countBlocks) * blockDim.x + threadIdx.x) >> 5;
    int nwarps = ((gridDim.x - countBlocks) * blockDim.x) >> 5;

    const float4* W = reinterpret_cast<const float4*>(W1);  // W1 row k -> float4
    float4 w0 = W[4 * lane + 0];
    float4 w1 = W[4 * lane + 1];
    float4 w2 = W[4 * lane + 2];
    float4 w3 = W[4 * lane + 3];

    const float4* x4 = reinterpret_cast<const float4*>(x);
    const unsigned FULL = 0xffffffffu;
    int npairs = (n + 1) >> 1;

    for (int pair = warp; pair < npairs; pair += nwarps) {
        int nodeA = pair * 2;
        int nodeB = nodeA + 1;
        bool hasB = nodeB < n;

        float4 xa = __ldcs(x4 + (size_t)nodeA * 32 + lane);
        float4 xb = hasB ? __ldcs(x4 + (size_t)nodeB * 32 + lane)
                         : make_float4(0.f, 0.f, 0.f, 0.f);

        float a0 = xa.x * w0.x + xa.y * w1.x + xa.z * w2.x + xa.w * w3.x;
        float a1 = xa.x * w0.y + xa.y * w1.y + xa.z * w2.y + xa.w * w3.y;
        float a2 = xa.x * w0.z + xa.y * w1.z + xa.z * w2.z + xa.w * w3.z;
        float a3 = xa.x * w0.w + xa.y * w1.w + xa.z * w2.w + xa.w * w3.w;
        float b0 = xb.x * w0.x + xb.y * w1.x + xb.z * w2.x + xb.w * w3.x;
        float b1 = xb.x * w0.y + xb.y * w1.y + xb.z * w2.y + xb.w * w3.y;
        float b2 = xb.x * w0.z + xb.y * w1.z + xb.z * w2.z + xb.w * w3.z;
        float b3 = xb.x * w0.w + xb.y * w1.w + xb.z * w2.w + xb.w * w3.w;

        a0 += __shfl_xor_sync(FULL, a0, 16); b0 += __shfl_xor_sync(FULL, b0, 16);
        a1 += __shfl_xor_sync(FULL, a1, 16); b1 += __shfl_xor_sync(FULL, b1, 16);
        a2 += __shfl_xor_sync(FULL, a2, 16); b2 += __shfl_xor_sync(FULL, b2, 16);
        a3 += __shfl_xor_sync(FULL, a3, 16); b3 += __shfl_xor_sync(FULL, b3, 16);
        a0 += __shfl_xor_sync(FULL, a0, 8);  b0 += __shfl_xor_sync(FULL, b0, 8);
        a1 += __shfl_xor_sync(FULL, a1, 8);  b1 += __shfl_xor_sync(FULL, b1, 8);
        a2 += __shfl_xor_sync(FULL, a2, 8);  b2 += __shfl_xor_sync(FULL, b2, 8);
        a3 += __shfl_xor_sync(FULL, a3, 8);  b3 += __shfl_xor_sync(FULL, b3, 8);

        int g = lane >> 3;
        float va = (g == 0) ? a0 : (g == 1) ? a1 : (g == 2) ? a2 : a3;
        float vb = (g == 0) ? b0 : (g == 1) ? b1 : (g == 2) ? b2 : b3;
        va += __shfl_xor_sync(FULL, va, 4);  vb += __shfl_xor_sync(FULL, vb, 4);
        va += __shfl_xor_sync(FULL, va, 2);  vb += __shfl_xor_sync(FULL, vb, 2);
        va += __shfl_xor_sync(FULL, va, 1);  vb += __shfl_xor_sync(FULL, vb, 1);

        int sub = lane & 7;
        bool isA = (sub == 0);
        bool isB = (sub == 4) && hasB;
        if (isA | isB) {
            int nod = isA ? nodeA : nodeB;
            float v = isA ? va : vb;
            reinterpret_cast<float*>(&g_proj[nod])[g] = v;  // raw, dinv in k_seed
        }
    }
}

// ---------------------------------------------------------------------------
// seed: dinv = rsqrt(deg); projd = raw*dinv; agg = projd
// ---------------------------------------------------------------------------
__global__ void k_seed(int n) {
    int i = blockIdx.x * blockDim.x + threadIdx.x;
    if (i >= n) return;
    float d = rsqrtf((float)g_deg[i]);
    g_dinv[i] = d;
    float4 p = g_proj[i];
    p.x *= d; p.y *= d; p.z *= d; p.w *= d;
    g_proj[i] = p;
    g_agg[i]  = p;
}

// ---------------------------------------------------------------------------
// Edge scatter (4-wide): sum[c] += projd[r].
// ---------------------------------------------------------------------------
__device__ __forceinline__ void red4(int r, int c) {
    float4 p = __ldcg(&g_proj[r]);
    asm volatile("red.global.add.v4.f32 [%0], {%1,%2,%3,%4};"
                 :: "l"(&g_agg[c]), "f"(p.x), "f"(p.y), "f"(p.z), "f"(p.w)
                 : "memory");
}

__global__ void k_scatter4(const int* __restrict__ row,
                           const int* __restrict__ col, int E) {
    int t = blockIdx.x * blockDim.x + threadIdx.x;
    int base = t * 8;
    if (base + 8 <= E) {
        int4 r0 = __ldcs(reinterpret_cast<const int4*>(row + base));
        int4 r1 = __ldcs(reinterpret_cast<const int4*>(row + base) + 1);
        int4 c0 = __ldcs(reinterpret_cast<const int4*>(col + base));
        int4 c1 = __ldcs(reinterpret_cast<const int4*>(col + base) + 1);
        red4(r0.x, c0.x); red4(r0.y, c0.y); red4(r0.z, c0.z); red4(r0.w, c0.w);
        red4(r1.x, c1.x); red4(r1.y, c1.y); red4(r1.z, c1.z); red4(r1.w, c1.w);
    } else if (base < E) {
        for (int j = base; j < E; j++) red4(__ldcs(row + j), __ldcs(col + j));
    }
}

// ---------------------------------------------------------------------------
// Layer 2: t = tanh(dinv*sum + b1); projd = (t @ W2) * dinv; reseed sum.
// ---------------------------------------------------------------------------
__global__ void k_proj2(const float* __restrict__ W2,
                        const float* __restrict__ b1, int n) {
    int i = blockIdx.x * blockDim.x + threadIdx.x;
    if (i >= n) return;
    float4 a = g_agg[i];
    float d = g_dinv[i];
    float t0 = tanhf(a.x * d + __ldg(&b1[0]));
    float t1 = tanhf(a.y * d + __ldg(&b1[1]));
    float t2 = tanhf(a.z * d + __ldg(&b1[2]));
    float t3 = tanhf(a.w * d + __ldg(&b1[3]));
    float4 p;
    p.x = (t0 * __ldg(&W2[0]) + t1 * __ldg(&W2[4]) + t2 * __ldg(&W2[8])  + t3 * __ldg(&W2[12])) * d;
    p.y = (t0 * __ldg(&W2[1]) + t1 * __ldg(&W2[5]) + t2 * __ldg(&W2[9])  + t3 * __ldg(&W2[13])) * d;
    p.z = (t0 * __ldg(&W2[2]) + t1 * __ldg(&W2[6]) + t2 * __ldg(&W2[10]) + t3 * __ldg(&W2[14])) * d;
    p.w = (t0 * __ldg(&W2[3]) + t1 * __ldg(&W2[7]) + t2 * __ldg(&W2[11]) + t3 * __ldg(&W2[15])) * d;
    g_proj[i] = p;
    g_agg[i]  = p;
}

// ---------------------------------------------------------------------------
// Layer 3: t = tanh(dinv*sum + b2); projd2 = (t @ W3) * dinv (2-wide).
// ---------------------------------------------------------------------------
__global__ void k_proj3(const float* __restrict__ W3,
                        const float* __restrict__ b2, int n) {
    int i = blockIdx.x * blockDim.x + threadIdx.x;
    if (i >= n) return;
    float4 a = g_agg[i];
    float d = g_dinv[i];
    float t0 = tanhf(a.x * d + __ldg(&b2[0]));
    float t1 = tanhf(a.y * d + __ldg(&b2[1]));
    float t2 = tanhf(a.z * d + __ldg(&b2[2]));
    float t3 = tanhf(a.w * d + __ldg(&b2[3]));
    float p0 = (t0 * __ldg(&W3[0]) + t1 * __ldg(&W3[2]) + t2 * __ldg(&W3[4]) + t3 * __ldg(&W3[6])) * d;
    float p1 = (t0 * __ldg(&W3[1]) + t1 * __ldg(&W3[3]) + t2 * __ldg(&W3[5]) + t3 * __ldg(&W3[7])) * d;
    float2 pd = make_float2(p0, p1);
    g_p2[i] = pd;
    g_a2[i] = pd;
}

__device__ __forceinline__ void red2(int r, int c) {
    float2 p = __ldcg(&g_p2[r]);
    asm volatile("red.global.add.v2.f32 [%0], {%1,%2};"
                 :: "l"(&g_a2[c]), "f"(p.x), "f"(p.y)
                 : "memory");
}

__global__ void k_scatter2(const int* __restrict__ row,
                           const int* __restrict__ col, int E) {
    int t = blockIdx.x * blockDim.x + threadIdx.x;
    int base = t * 8;
    if (base + 8 <= E) {
        int4 r0 = __ldcs(reinterpret_cast<const int4*>(row + base));
        int4 r1 = __ldcs(reinterpret_cast<const int4*>(row + base) + 1);
        int4 c0 = __ldcs(reinterpret_cast<const int4*>(col + base));
        int4 c1 = __ldcs(reinterpret_cast<const int4*>(col + base) + 1);
        red2(r0.x, c0.x); red2(r0.y, c0.y); red2(r0.z, c0.z); red2(r0.w, c0.w);
        red2(r1.x, c1.x); red2(r1.y, c1.y); red2(r1.z, c1.z); red2(r1.w, c1.w);
    } else if (base < E) {
        for (int j = base; j < E; j++) red2(__ldcs(row + j), __ldcs(col + j));
    }
}

// ---------------------------------------------------------------------------
// Epilogue: h = tanh(dinv*sum + b3); out = h @ Wc + bc.
// d_out: out[N,16] then h[N,2].  Coalesced writes via smem staging.
// ---------------------------------------------------------------------------
__global__ void k_final(const float* __restrict__ Wc,
                        const float* __restrict__ b3,
                        const float* __restrict__ bc,
                        float* __restrict__ out, int n) {
    __shared__ float sh0[256];
    __shared__ float sh1[256];
    int node = blockIdx.x * 256 + threadIdx.x;
    float h0 = 0.f, h1 = 0.f;
    if (node < n) {
        float2 a = g_a2[node];
        float d = g_dinv[node];
        h0 = tanhf(a.x * d + __ldg(&b3[0]));
        h1 = tanhf(a.y * d + __ldg(&b3[1]));
        float2* hp = reinterpret_cast<float2*>(out + (size_t)16 * n);
        __stcs(hp + node, make_float2(h0, h1));
    }
    sh0[threadIdx.x] = h0;
    sh1[threadIdx.x] = h1;
    __syncthreads();

    int blockNodes = min(256, n - (int)blockIdx.x * 256);
    if (blockNodes <= 0) return;
    float4* o4 = reinterpret_cast<float4*>(out + (size_t)blockIdx.x * 256 * 16);
    for (int idx = threadIdx.x; idx < blockNodes * 4; idx += 256) {
        int nd = idx >> 2;
        int j  = (idx & 3) * 4;
        float H0 = sh0[nd], H1 = sh1[nd];
        float4 v;
        v.x = H0 * __ldg(&Wc[j + 0]) + H1 * __ldg(&Wc[16 + j + 0]) + __ldg(&bc[j + 0]);
        v.y = H0 * __ldg(&Wc[j + 1]) + H1 * __ldg(&Wc[16 + j + 1]) + __ldg(&bc[j + 1]);
        v.z = H0 * __ldg(&Wc[j + 2]) + H1 * __ldg(&Wc[16 + j + 2]) + __ldg(&bc[j + 2]);
        v.w = H0 * __ldg(&Wc[j + 3]) + H1 * __ldg(&Wc[16 + j + 3]) + __ldg(&bc[j + 3]);
        __stcs(o4 + idx, v);
    }
}

// ---------------------------------------------------------------------------
// Launch
// ---------------------------------------------------------------------------
extern "C" void kernel_launch(void* const* d_in, const int* in_sizes, int n_in,
                              void* d_out, int out_size) {
    const float* x  = (const float*)d_in[0];
    const int*   ei = (const int*)d_in[1];
    const float* W1 = (const float*)d_in[2];
    const float* b1 = (const float*)d_in[3];
    const float* W2 = (const float*)d_in[4];
    const float* b2 = (const float*)d_in[5];
    const float* W3 = (const float*)d_in[6];
    const float* b3 = (const float*)d_in[7];
    const float* Wc = (const float*)d_in[8];
    const float* bc = (const float*)d_in[9];
    float* out = (float*)d_out;

    const int n = in_sizes[0] / 128;
    const int E = in_sizes[1] / 2;
    const int* row = ei;       // source
    const int* col = ei + E;   // target

    const int TB = 256;
    int nodeBlocks = (n + TB - 1) / TB;
    int edgeBlocks = ((E + 7) / 8 + TB - 1) / TB;

    const int COUNT_BLOCKS = 148 * 2;  // LTS-bound half
    const int PROJ_BLOCKS  = 148 * 4;  // DRAM-bound half (6 blocks/SM total)

    k_init_deg<<<nodeBlocks, TB>>>(n);

    // degree count || layer-1 raw projection
    k_count_proj1<<<COUNT_BLOCKS + PROJ_BLOCKS, TB>>>(x, W1, col, n, E, COUNT_BLOCKS);
    k_seed<<<nodeBlocks, TB>>>(n);

    // layer 1 aggregate
    k_scatter4<<<edgeBlocks, TB>>>(row, col, E);

    // layer 2
    k_proj2<<<nodeBlocks, TB>>>(W2, b1, n);
    k_scatter4<<<edgeBlocks, TB>>>(row, col, E);

    // layer 3
    k_proj3<<<nodeBlocks, TB>>>(W3, b2, n);
    k_scatter2<<<edgeBlocks, TB>>>(row, col, E);

    // classifier epilogue
    k_final<<<nodeBlocks, TB>>>(Wc, b3, bc, out, n);
}

// round 6
// speedup vs baseline: 1.4877x; 1.0296x over previous
#include <cuda_runtime.h>
#include <cstdint>

#define NMAX 1000000

// Scratch (__device__ globals; no allocation allowed)
__device__ float4   g_proj[NMAX];   // projd (layers 1,2); layer-1 raw before seed
__device__ float4   g_agg[NMAX];    // running sum (seeded with projd[self])
__device__ float    g_dinv[NMAX];   // rsqrt(deg)
__device__ unsigned g_deg[NMAX];    // integer degree
__device__ float2   g_p2[NMAX];     // layer-3 projd (2-wide)
__device__ float2   g_a2[NMAX];     // layer-3 sum

// ---------------------------------------------------------------------------
// degree
// ---------------------------------------------------------------------------
__global__ void k_init_deg(int n) {
    int i = blockIdx.x * blockDim.x + threadIdx.x;
    if (i < n) g_deg[i] = 1u;  // self-loop
}

__device__ __forceinline__ void red_cnt(int c) {
    unsigned one = 1u;
    asm volatile("red.global.add.u32 [%0], %1;" :: "l"(&g_deg[c]), "r"(one) : "memory");
}

__global__ void k_count(const int* __restrict__ col, int E) {
    int t = blockIdx.x * blockDim.x + threadIdx.x;
    int base = t * 16;
    if (base + 16 <= E) {
        const int4* c4 = reinterpret_cast<const int4*>(col + base);
        int4 c0 = __ldcs(c4 + 0);
        int4 c1 = __ldcs(c4 + 1);
        int4 c2 = __ldcs(c4 + 2);
        int4 c3 = __ldcs(c4 + 3);
        red_cnt(c0.x); red_cnt(c0.y); red_cnt(c0.z); red_cnt(c0.w);
        red_cnt(c1.x); red_cnt(c1.y); red_cnt(c1.z); red_cnt(c1.w);
        red_cnt(c2.x); red_cnt(c2.y); red_cnt(c2.z); red_cnt(c2.w);
        red_cnt(c3.x); red_cnt(c3.y); red_cnt(c3.z); red_cnt(c3.w);
    } else if (base < E) {
        for (int j = base; j < E; j++) red_cnt(__ldcs(col + j));
    }
}

// ---------------------------------------------------------------------------
// Layer 1 RAW projection: g_proj = x @ W1 (no dinv).  Warp handles 2 nodes,
// W in registers, 11-shuffle transpose reduction per node.
// Independent of the degree pass -> runs on a parallel graph branch.
// ---------------------------------------------------------------------------
__global__ void __launch_bounds__(256, 5)
k_proj1(const float* __restrict__ x, const float* __restrict__ W1, int n) {
    int lane = threadIdx.x & 31;
    int warp = (blockIdx.x * blockDim.x + threadIdx.x) >> 5;
    int nwarps = (gridDim.x * blockDim.x) >> 5;

    const float4* W = reinterpret_cast<const float4*>(W1);  // W1 row k -> float4
    float4 w0 = W[4 * lane + 0];
    float4 w1 = W[4 * lane + 1];
    float4 w2 = W[4 * lane + 2];
    float4 w3 = W[4 * lane + 3];

    const float4* x4 = reinterpret_cast<const float4*>(x);
    const unsigned FULL = 0xffffffffu;
    int npairs = (n + 1) >> 1;

    for (int pair = warp; pair < npairs; pair += nwarps) {
        int nodeA = pair * 2;
        int nodeB = nodeA + 1;
        bool hasB = nodeB < n;

        float4 xa = __ldcs(x4 + (size_t)nodeA * 32 + lane);
        float4 xb = hasB ? __ldcs(x4 + (size_t)nodeB * 32 + lane)
                         : make_float4(0.f, 0.f, 0.f, 0.f);

        float a0 = xa.x * w0.x + xa.y * w1.x + xa.z * w2.x + xa.w * w3.x;
        float a1 = xa.x * w0.y + xa.y * w1.y + xa.z * w2.y + xa.w * w3.y;
        float a2 = xa.x * w0.z + xa.y * w1.z + xa.z * w2.z + xa.w * w3.z;
        float a3 = xa.x * w0.w + xa.y * w1.w + xa.z * w2.w + xa.w * w3.w;
        float b0 = xb.x * w0.x + xb.y * w1.x + xb.z * w2.x + xb.w * w3.x;
        float b1 = xb.x * w0.y + xb.y * w1.y + xb.z * w2.y + xb.w * w3.y;
        float b2 = xb.x * w0.z + xb.y * w1.z + xb.z * w2.z + xb.w * w3.z;
        float b3 = xb.x * w0.w + xb.y * w1.w + xb.z * w2.w + xb.w * w3.w;

        a0 += __shfl_xor_sync(FULL, a0, 16); b0 += __shfl_xor_sync(FULL, b0, 16);
        a1 += __shfl_xor_sync(FULL, a1, 16); b1 += __shfl_xor_sync(FULL, b1, 16);
        a2 += __shfl_xor_sync(FULL, a2, 16); b2 += __shfl_xor_sync(FULL, b2, 16);
        a3 += __shfl_xor_sync(FULL, a3, 16); b3 += __shfl_xor_sync(FULL, b3, 16);
        a0 += __shfl_xor_sync(FULL, a0, 8);  b0 += __shfl_xor_sync(FULL, b0, 8);
        a1 += __shfl_xor_sync(FULL, a1, 8);  b1 += __shfl_xor_sync(FULL, b1, 8);
        a2 += __shfl_xor_sync(FULL, a2, 8);  b2 += __shfl_xor_sync(FULL, b2, 8);
        a3 += __shfl_xor_sync(FULL, a3, 8);  b3 += __shfl_xor_sync(FULL, b3, 8);

        int g = lane >> 3;
        float va = (g == 0) ? a0 : (g == 1) ? a1 : (g == 2) ? a2 : a3;
        float vb = (g == 0) ? b0 : (g == 1) ? b1 : (g == 2) ? b2 : b3;
        va += __shfl_xor_sync(FULL, va, 4);  vb += __shfl_xor_sync(FULL, vb, 4);
        va += __shfl_xor_sync(FULL, va, 2);  vb += __shfl_xor_sync(FULL, vb, 2);
        va += __shfl_xor_sync(FULL, va, 1);  vb += __shfl_xor_sync(FULL, vb, 1);

        int sub = lane & 7;
        bool isA = (sub == 0);
        bool isB = (sub == 4) && hasB;
        if (isA | isB) {
            int nod = isA ? nodeA : nodeB;
            float v = isA ? va : vb;
            reinterpret_cast<float*>(&g_proj[nod])[g] = v;  // raw; scaled in k_seed
        }
    }
}

// ---------------------------------------------------------------------------
// join: dinv = rsqrt(deg); projd = raw*dinv; agg = projd
// ---------------------------------------------------------------------------
__global__ void k_seed(int n) {
    int i = blockIdx.x * blockDim.x + threadIdx.x;
    if (i >= n) return;
    float d = rsqrtf((float)g_deg[i]);
    g_dinv[i] = d;
    float4 p = g_proj[i];
    p.x *= d; p.y *= d; p.z *= d; p.w *= d;
    g_proj[i] = p;
    g_agg[i]  = p;
}

// ---------------------------------------------------------------------------
// Edge scatter (4-wide): sum[c] += projd[r].  16 edges/thread.
// ---------------------------------------------------------------------------
__device__ __forceinline__ void red4(int r, int c) {
    float4 p = __ldcg(&g_proj[r]);
    asm volatile("red.global.add.v4.f32 [%0], {%1,%2,%3,%4};"
                 :: "l"(&g_agg[c]), "f"(p.x), "f"(p.y), "f"(p.z), "f"(p.w)
                 : "memory");
}

__global__ void k_scatter4(const int* __restrict__ row,
                           const int* __restrict__ col, int E) {
    int t = blockIdx.x * blockDim.x + threadIdx.x;
    int base = t * 16;
    if (base + 16 <= E) {
        const int4* r4 = reinterpret_cast<const int4*>(row + base);
        const int4* c4 = reinterpret_cast<const int4*>(col + base);
        int4 r0 = __ldcs(r4 + 0), r1 = __ldcs(r4 + 1), r2 = __ldcs(r4 + 2), r3 = __ldcs(r4 + 3);
        int4 c0 = __ldcs(c4 + 0), c1 = __ldcs(c4 + 1), c2 = __ldcs(c4 + 2), c3 = __ldcs(c4 + 3);
        red4(r0.x, c0.x); red4(r0.y, c0.y); red4(r0.z, c0.z); red4(r0.w, c0.w);
        red4(r1.x, c1.x); red4(r1.y, c1.y); red4(r1.z, c1.z); red4(r1.w, c1.w);
        red4(r2.x, c2.x); red4(r2.y, c2.y); red4(r2.z, c2.z); red4(r2.w, c2.w);
        red4(r3.x, c3.x); red4(r3.y, c3.y); red4(r3.z, c3.z); red4(r3.w, c3.w);
    } else if (base < E) {
        for (int j = base; j < E; j++) red4(__ldcs(row + j), __ldcs(col + j));
    }
}

// ---------------------------------------------------------------------------
// Layer 2: t = tanh(dinv*sum + b1); projd = (t @ W2) * dinv; reseed sum.
// ---------------------------------------------------------------------------
__global__ void k_proj2(const float* __restrict__ W2,
                        const float* __restrict__ b1, int n) {
    int i = blockIdx.x * blockDim.x + threadIdx.x;
    if (i >= n) return;
    float4 a = g_agg[i];
    float d = g_dinv[i];
    float t0 = tanhf(a.x * d + __ldg(&b1[0]));
    float t1 = tanhf(a.y * d + __ldg(&b1[1]));
    float t2 = tanhf(a.z * d + __ldg(&b1[2]));
    float t3 = tanhf(a.w * d + __ldg(&b1[3]));
    float4 p;
    p.x = (t0 * __ldg(&W2[0]) + t1 * __ldg(&W2[4]) + t2 * __ldg(&W2[8])  + t3 * __ldg(&W2[12])) * d;
    p.y = (t0 * __ldg(&W2[1]) + t1 * __ldg(&W2[5]) + t2 * __ldg(&W2[9])  + t3 * __ldg(&W2[13])) * d;
    p.z = (t0 * __ldg(&W2[2]) + t1 * __ldg(&W2[6]) + t2 * __ldg(&W2[10]) + t3 * __ldg(&W2[14])) * d;
    p.w = (t0 * __ldg(&W2[3]) + t1 * __ldg(&W2[7]) + t2 * __ldg(&W2[11]) + t3 * __ldg(&W2[15])) * d;
    g_proj[i] = p;
    g_agg[i]  = p;
}

// ---------------------------------------------------------------------------
// Layer 3: t = tanh(dinv*sum + b2); projd2 = (t @ W3) * dinv (2-wide).
// ---------------------------------------------------------------------------
__global__ void k_proj3(const float* __restrict__ W3,
                        const float* __restrict__ b2, int n) {
    int i = blockIdx.x * blockDim.x + threadIdx.x;
    if (i >= n) return;
    float4 a = g_agg[i];
    float d = g_dinv[i];
    float t0 = tanhf(a.x * d + __ldg(&b2[0]));
    float t1 = tanhf(a.y * d + __ldg(&b2[1]));
    float t2 = tanhf(a.z * d + __ldg(&b2[2]));
    float t3 = tanhf(a.w * d + __ldg(&b2[3]));
    float p0 = (t0 * __ldg(&W3[0]) + t1 * __ldg(&W3[2]) + t2 * __ldg(&W3[4]) + t3 * __ldg(&W3[6])) * d;
    float p1 = (t0 * __ldg(&W3[1]) + t1 * __ldg(&W3[3]) + t2 * __ldg(&W3[5]) + t3 * __ldg(&W3[7])) * d;
    float2 pd = make_float2(p0, p1);
    g_p2[i] = pd;
    g_a2[i] = pd;
}

__device__ __forceinline__ void red2(int r, int c) {
    float2 p = __ldcg(&g_p2[r]);
    asm volatile("red.global.add.v2.f32 [%0], {%1,%2};"
                 :: "l"(&g_a2[c]), "f"(p.x), "f"(p.y)
                 : "memory");
}

__global__ void k_scatter2(const int* __restrict__ row,
                           const int* __restrict__ col, int E) {
    int t = blockIdx.x * blockDim.x + threadIdx.x;
    int base = t * 16;
    if (base + 16 <= E) {
        const int4* r4 = reinterpret_cast<const int4*>(row + base);
        const int4* c4 = reinterpret_cast<const int4*>(col + base);
        int4 r0 = __ldcs(r4 + 0), r1 = __ldcs(r4 + 1), r2 = __ldcs(r4 + 2), r3 = __ldcs(r4 + 3);
        int4 c0 = __ldcs(c4 + 0), c1 = __ldcs(c4 + 1), c2 = __ldcs(c4 + 2), c3 = __ldcs(c4 + 3);
        red2(r0.x, c0.x); red2(r0.y, c0.y); red2(r0.z, c0.z); red2(r0.w, c0.w);
        red2(r1.x, c1.x); red2(r1.y, c1.y); red2(r1.z, c1.z); red2(r1.w, c1.w);
        red2(r2.x, c2.x); red2(r2.y, c2.y); red2(r2.z, c2.z); red2(r2.w, c2.w);
        red2(r3.x, c3.x); red2(r3.y, c3.y); red2(r3.z, c3.z); red2(r3.w, c3.w);
    } else if (base < E) {
        for (int j = base; j < E; j++) red2(__ldcs(row + j), __ldcs(col + j));
    }
}

// ---------------------------------------------------------------------------
// Epilogue: h = tanh(dinv*sum + b3); out = h @ Wc + bc.
// d_out: out[N,16] then h[N,2].  Coalesced writes via smem staging.
// ---------------------------------------------------------------------------
__global__ void k_final(const float* __restrict__ Wc,
                        const float* __restrict__ b3,
                        const float* __restrict__ bc,
                        float* __restrict__ out, int n) {
    __shared__ float sh0[256];
    __shared__ float sh1[256];
    int node = blockIdx.x * 256 + threadIdx.x;
    float h0 = 0.f, h1 = 0.f;
    if (node < n) {
        float2 a = g_a2[node];
        float d = g_dinv[node];
        h0 = tanhf(a.x * d + __ldg(&b3[0]));
        h1 = tanhf(a.y * d + __ldg(&b3[1]));
        float2* hp = reinterpret_cast<float2*>(out + (size_t)16 * n);
        __stcs(hp + node, make_float2(h0, h1));
    }
    sh0[threadIdx.x] = h0;
    sh1[threadIdx.x] = h1;
    __syncthreads();

    int blockNodes = min(256, n - (int)blockIdx.x * 256);
    if (blockNodes <= 0) return;
    float4* o4 = reinterpret_cast<float4*>(out + (size_t)blockIdx.x * 256 * 16);
    for (int idx = threadIdx.x; idx < blockNodes * 4; idx += 256) {
        int nd = idx >> 2;
        int j  = (idx & 3) * 4;
        float H0 = sh0[nd], H1 = sh1[nd];
        float4 v;
        v.x = H0 * __ldg(&Wc[j + 0]) + H1 * __ldg(&Wc[16 + j + 0]) + __ldg(&bc[j + 0]);
        v.y = H0 * __ldg(&Wc[j + 1]) + H1 * __ldg(&Wc[16 + j + 1]) + __ldg(&bc[j + 1]);
        v.z = H0 * __ldg(&Wc[j + 2]) + H1 * __ldg(&Wc[16 + j + 2]) + __ldg(&bc[j + 2]);
        v.w = H0 * __ldg(&Wc[j + 3]) + H1 * __ldg(&Wc[16 + j + 3]) + __ldg(&bc[j + 3]);
        __stcs(o4 + idx, v);
    }
}

// ---------------------------------------------------------------------------
// Launch (fork-join capture: count || proj1)
// ---------------------------------------------------------------------------
extern "C" void kernel_launch(void* const* d_in, const int* in_sizes, int n_in,
                              void* d_out, int out_size) {
    const float* x  = (const float*)d_in[0];
    const int*   ei = (const int*)d_in[1];
    const float* W1 = (const float*)d_in[2];
    const float* b1 = (const float*)d_in[3];
    const float* W2 = (const float*)d_in[4];
    const float* b2 = (const float*)d_in[5];
    const float* W3 = (const float*)d_in[6];
    const float* b3 = (const float*)d_in[7];
    const float* Wc = (const float*)d_in[8];
    const float* bc = (const float*)d_in[9];
    float* out = (float*)d_out;

    const int n = in_sizes[0] / 128;
    const int E = in_sizes[1] / 2;
    const int* row = ei;       // source
    const int* col = ei + E;   // target

    const int TB = 256;
    int nodeBlocks  = (n + TB - 1) / TB;
    int edgeBlocks  = ((E + 15) / 16 + TB - 1) / TB;
    int projBlocks  = 148 * 5;

    // Host-side reusable fork stream + events (host objects; created once,
    // outside any capture region on the first/correctness call).
    static cudaStream_t s2 = nullptr;
    static cudaEvent_t  eFork = nullptr, eJoin = nullptr;
    if (s2 == nullptr) {
        cudaStreamCreateWithFlags(&s2, cudaStreamNonBlocking);
        cudaEventCreateWithFlags(&eFork, cudaEventDisableTiming);
        cudaEventCreateWithFlags(&eJoin, cudaEventDisableTiming);
    }

    // Fork: branch B (proj1 raw) runs concurrently with branch A (init+count).
    cudaEventRecord(eFork, 0);
    cudaStreamWaitEvent(s2, eFork, 0);
    k_proj1<<<projBlocks, TB, 0, s2>>>(x, W1, n);          // branch B
    k_init_deg<<<nodeBlocks, TB>>>(n);                     // branch A
    k_count<<<edgeBlocks, TB>>>(col, E);                   // branch A
    cudaEventRecord(eJoin, s2);
    cudaStreamWaitEvent(0, eJoin, 0);

    // Join: scale by dinv, seed agg
    k_seed<<<nodeBlocks, TB>>>(n);

    // layer 1 aggregate
    k_scatter4<<<edgeBlocks, TB>>>(row, col, E);

    // layer 2
    k_proj2<<<nodeBlocks, TB>>>(W2, b1, n);
    k_scatter4<<<edgeBlocks, TB>>>(row, col, E);

    // layer 3
    k_proj3<<<nodeBlocks, TB>>>(W3, b2, n);
    k_scatter2<<<edgeBlocks, TB>>>(row, col, E);

    // classifier epilogue
    k_final<<<nodeBlocks, TB>>>(Wc, b3, bc, out, n);
}

// round 7
// speedup vs baseline: 1.5281x; 1.0272x over previous
#include <cuda_runtime.h>
#include <cstdint>

#define NMAX 1000000

// Scratch (__device__ globals; no allocation allowed)
__device__ float4 g_proj[NMAX];    // projd = proj * dinv   (layers 1,2)
__device__ float4 g_agg[NMAX];     // running sum (seeded with projd[self])
__device__ float  g_dinv[NMAX];    // holds DEGREE (consumers apply rsqrtf)
__device__ float2 g_p2[NMAX];      // layer-3 projd (2-wide)
__device__ float2 g_a2[NMAX];      // layer-3 sum

// ---------------------------------------------------------------------------
// degree
// ---------------------------------------------------------------------------
__global__ void k_init_deg(int n) {
    int i = blockIdx.x * blockDim.x + threadIdx.x;
    if (i < n) g_dinv[i] = 1.0f;  // self-loop
}

__device__ __forceinline__ void red_deg(int c) {
    asm volatile("red.global.add.f32 [%0], %1;" :: "l"(&g_dinv[c]), "f"(1.0f) : "memory");
}

__global__ void k_count_deg(const int* __restrict__ col, int E) {
    int t = blockIdx.x * blockDim.x + threadIdx.x;
    int base = t * 8;
    if (base + 8 <= E) {
        int4 c0 = __ldcs(reinterpret_cast<const int4*>(col + base));
        int4 c1 = __ldcs(reinterpret_cast<const int4*>(col + base) + 1);
        red_deg(c0.x); red_deg(c0.y); red_deg(c0.z); red_deg(c0.w);
        red_deg(c1.x); red_deg(c1.y); red_deg(c1.z); red_deg(c1.w);
    } else if (base < E) {
        for (int j = base; j < E; j++) red_deg(__ldcs(col + j));
    }
}

// ---------------------------------------------------------------------------
// Layer 1: projd = (x @ W1) * rsqrt(deg).  Warp handles 4 nodes/iter
// (4 independent 128B loads in flight), W in registers, 11 shuffles/node.
// Seeds agg = projd (self-loop term).
// ---------------------------------------------------------------------------
#define PROJ1_REDUCE(s) \
    a0 += __shfl_xor_sync(FULL, a0, s); b0 += __shfl_xor_sync(FULL, b0, s); \
    c0 += __shfl_xor_sync(FULL, c0, s); d0 += __shfl_xor_sync(FULL, d0, s); \
    a1 += __shfl_xor_sync(FULL, a1, s); b1 += __shfl_xor_sync(FULL, b1, s); \
    c1 += __shfl_xor_sync(FULL, c1, s); d1 += __shfl_xor_sync(FULL, d1, s); \
    a2 += __shfl_xor_sync(FULL, a2, s); b2 += __shfl_xor_sync(FULL, b2, s); \
    c2 += __shfl_xor_sync(FULL, c2, s); d2 += __shfl_xor_sync(FULL, d2, s); \
    a3 += __shfl_xor_sync(FULL, a3, s); b3 += __shfl_xor_sync(FULL, b3, s); \
    c3 += __shfl_xor_sync(FULL, c3, s); d3 += __shfl_xor_sync(FULL, d3, s);

__global__ void __launch_bounds__(256, 3)
k_proj1(const float* __restrict__ x, const float* __restrict__ W1, int n) {
    int lane = threadIdx.x & 31;
    int warp = (blockIdx.x * blockDim.x + threadIdx.x) >> 5;
    int nwarps = (gridDim.x * blockDim.x) >> 5;

    const float4* W = reinterpret_cast<const float4*>(W1);  // W1 row k -> float4
    float4 w0 = W[4 * lane + 0];
    float4 w1 = W[4 * lane + 1];
    float4 w2 = W[4 * lane + 2];
    float4 w3 = W[4 * lane + 3];

    const float4* x4 = reinterpret_cast<const float4*>(x);
    const unsigned FULL = 0xffffffffu;
    int nquads = (n + 3) >> 2;

    for (int q = warp; q < nquads; q += nwarps) {
        int nodeA = q * 4;
        int nodeB = nodeA + 1, nodeC = nodeA + 2, nodeD = nodeA + 3;
        bool hasB = nodeB < n, hasC = nodeC < n, hasD = nodeD < n;
        const float4 Z = make_float4(0.f, 0.f, 0.f, 0.f);

        // 4 independent 128B loads in flight
        float4 xa = __ldcs(x4 + (size_t)nodeA * 32 + lane);
        float4 xb = hasB ? __ldcs(x4 + (size_t)nodeB * 32 + lane) : Z;
        float4 xc = hasC ? __ldcs(x4 + (size_t)nodeC * 32 + lane) : Z;
        float4 xd = hasD ? __ldcs(x4 + (size_t)nodeD * 32 + lane) : Z;

        float a0 = xa.x * w0.x + xa.y * w1.x + xa.z * w2.x + xa.w * w3.x;
        float a1 = xa.x * w0.y + xa.y * w1.y + xa.z * w2.y + xa.w * w3.y;
        float a2 = xa.x * w0.z + xa.y * w1.z + xa.z * w2.z + xa.w * w3.z;
        float a3 = xa.x * w0.w + xa.y * w1.w + xa.z * w2.w + xa.w * w3.w;
        float b0 = xb.x * w0.x + xb.y * w1.x + xb.z * w2.x + xb.w * w3.x;
        float b1 = xb.x * w0.y + xb.y * w1.y + xb.z * w2.y + xb.w * w3.y;
        float b2 = xb.x * w0.z + xb.y * w1.z + xb.z * w2.z + xb.w * w3.z;
        float b3 = xb.x * w0.w + xb.y * w1.w + xb.z * w2.w + xb.w * w3.w;
        float c0 = xc.x * w0.x + xc.y * w1.x + xc.z * w2.x + xc.w * w3.x;
        float c1 = xc.x * w0.y + xc.y * w1.y + xc.z * w2.y + xc.w * w3.y;
        float c2 = xc.x * w0.z + xc.y * w1.z + xc.z * w2.z + xc.w * w3.z;
        float c3 = xc.x * w0.w + xc.y * w1.w + xc.z * w2.w + xc.w * w3.w;
        float d0 = xd.x * w0.x + xd.y * w1.x + xd.z * w2.x + xd.w * w3.x;
        float d1 = xd.x * w0.y + xd.y * w1.y + xd.z * w2.y + xd.w * w3.y;
        float d2 = xd.x * w0.z + xd.y * w1.z + xd.z * w2.z + xd.w * w3.z;
        float d3 = xd.x * w0.w + xd.y * w1.w + xd.z * w2.w + xd.w * w3.w;

        PROJ1_REDUCE(16)
        PROJ1_REDUCE(8)

        // lane group g = lane>>3 owns output component g
        int g = lane >> 3;
        float va = (g == 0) ? a0 : (g == 1) ? a1 : (g == 2) ? a2 : a3;
        float vb = (g == 0) ? b0 : (g == 1) ? b1 : (g == 2) ? b2 : b3;
        float vc = (g == 0) ? c0 : (g == 1) ? c1 : (g == 2) ? c2 : c3;
        float vd = (g == 0) ? d0 : (g == 1) ? d1 : (g == 2) ? d2 : d3;
        va += __shfl_xor_sync(FULL, va, 4);  vb += __shfl_xor_sync(FULL, vb, 4);
        vc += __shfl_xor_sync(FULL, vc, 4);  vd += __shfl_xor_sync(FULL, vd, 4);
        va += __shfl_xor_sync(FULL, va, 2);  vb += __shfl_xor_sync(FULL, vb, 2);
        vc += __shfl_xor_sync(FULL, vc, 2);  vd += __shfl_xor_sync(FULL, vd, 2);
        va += __shfl_xor_sync(FULL, va, 1);  vb += __shfl_xor_sync(FULL, vb, 1);
        vc += __shfl_xor_sync(FULL, vc, 1);  vd += __shfl_xor_sync(FULL, vd, 1);
        // every lane in each 8-group holds the full sum for component g

        int sub = lane & 7;
        int nod = -1; float v = 0.f;
        if (sub == 0)              { nod = nodeA; v = va; }
        else if (sub == 2 && hasB) { nod = nodeB; v = vb; }
        else if (sub == 4 && hasC) { nod = nodeC; v = vc; }
        else if (sub == 6 && hasD) { nod = nodeD; v = vd; }
        if (nod >= 0) {
            float d  = rsqrtf(__ldg(&g_dinv[nod]));
            float pv = v * d;
            reinterpret_cast<float*>(&g_proj[nod])[g] = pv;
            reinterpret_cast<float*>(&g_agg[nod])[g]  = pv;
        }
    }
}

// ---------------------------------------------------------------------------
// Edge scatter (4-wide): sum[c] += projd[r].  8 edges/thread (measured best).
// ---------------------------------------------------------------------------
__device__ __forceinline__ void red4(int r, int c) {
    float4 p = __ldcg(&g_proj[r]);
    asm volatile("red.global.add.v4.f32 [%0], {%1,%2,%3,%4};"
                 :: "l"(&g_agg[c]), "f"(p.x), "f"(p.y), "f"(p.z), "f"(p.w)
                 : "memory");
}

__global__ void k_scatter4(const int* __restrict__ row,
                           const int* __restrict__ col, int E) {
    int t = blockIdx.x * blockDim.x + threadIdx.x;
    int base = t * 8;
    if (base + 8 <= E) {
        int4 r0 = __ldcs(reinterpret_cast<const int4*>(row + base));
        int4 r1 = __ldcs(reinterpret_cast<const int4*>(row + base) + 1);
        int4 c0 = __ldcs(reinterpret_cast<const int4*>(col + base));
        int4 c1 = __ldcs(reinterpret_cast<const int4*>(col + base) + 1);
        red4(r0.x, c0.x); red4(r0.y, c0.y); red4(r0.z, c0.z); red4(r0.w, c0.w);
        red4(r1.x, c1.x); red4(r1.y, c1.y); red4(r1.z, c1.z); red4(r1.w, c1.w);
    } else if (base < E) {
        for (int j = base; j < E; j++) red4(__ldcs(row + j), __ldcs(col + j));
    }
}

// ---------------------------------------------------------------------------
// Layer 2: t = tanh(dinv*sum + b1); projd = (t @ W2) * dinv; reseed sum.
// ---------------------------------------------------------------------------
__global__ void k_proj2(const float* __restrict__ W2,
                        const float* __restrict__ b1, int n) {
    int i = blockIdx.x * blockDim.x + threadIdx.x;
    if (i >= n) return;
    float4 a = g_agg[i];
    float d = rsqrtf(g_dinv[i]);
    float t0 = tanhf(a.x * d + __ldg(&b1[0]));
    float t1 = tanhf(a.y * d + __ldg(&b1[1]));
    float t2 = tanhf(a.z * d + __ldg(&b1[2]));
    float t3 = tanhf(a.w * d + __ldg(&b1[3]));
    float4 p;
    p.x = (t0 * __ldg(&W2[0]) + t1 * __ldg(&W2[4]) + t2 * __ldg(&W2[8])  + t3 * __ldg(&W2[12])) * d;
    p.y = (t0 * __ldg(&W2[1]) + t1 * __ldg(&W2[5]) + t2 * __ldg(&W2[9])  + t3 * __ldg(&W2[13])) * d;
    p.z = (t0 * __ldg(&W2[2]) + t1 * __ldg(&W2[6]) + t2 * __ldg(&W2[10]) + t3 * __ldg(&W2[14])) * d;
    p.w = (t0 * __ldg(&W2[3]) + t1 * __ldg(&W2[7]) + t2 * __ldg(&W2[11]) + t3 * __ldg(&W2[15])) * d;
    g_proj[i] = p;
    g_agg[i]  = p;
}

// ---------------------------------------------------------------------------
// Layer 3: t = tanh(dinv*sum + b2); projd2 = (t @ W3) * dinv (2-wide).
// ---------------------------------------------------------------------------
__global__ void k_proj3(const float* __restrict__ W3,
                        const float* __restrict__ b2, int n) {
    int i = blockIdx.x * blockDim.x + threadIdx.x;
    if (i >= n) return;
    float4 a = g_agg[i];
    float d = rsqrtf(g_dinv[i]);
    float t0 = tanhf(a.x * d + __ldg(&b2[0]));
    float t1 = tanhf(a.y * d + __ldg(&b2[1]));
    float t2 = tanhf(a.z * d + __ldg(&b2[2]));
    float t3 = tanhf(a.w * d + __ldg(&b2[3]));
    float p0 = (t0 * __ldg(&W3[0]) + t1 * __ldg(&W3[2]) + t2 * __ldg(&W3[4]) + t3 * __ldg(&W3[6])) * d;
    float p1 = (t0 * __ldg(&W3[1]) + t1 * __ldg(&W3[3]) + t2 * __ldg(&W3[5]) + t3 * __ldg(&W3[7])) * d;
    float2 pd = make_float2(p0, p1);
    g_p2[i] = pd;
    g_a2[i] = pd;
}

__device__ __forceinline__ void red2(int r, int c) {
    float2 p = __ldcg(&g_p2[r]);
    asm volatile("red.global.add.v2.f32 [%0], {%1,%2};"
                 :: "l"(&g_a2[c]), "f"(p.x), "f"(p.y)
                 : "memory");
}

__global__ void k_scatter2(const int* __restrict__ row,
                           const int* __restrict__ col, int E) {
    int t = blockIdx.x * blockDim.x + threadIdx.x;
    int base = t * 8;
    if (base + 8 <= E) {
        int4 r0 = __ldcs(reinterpret_cast<const int4*>(row + base));
        int4 r1 = __ldcs(reinterpret_cast<const int4*>(row + base) + 1);
        int4 c0 = __ldcs(reinterpret_cast<const int4*>(col + base));
        int4 c1 = __ldcs(reinterpret_cast<const int4*>(col + base) + 1);
        red2(r0.x, c0.x); red2(r0.y, c0.y); red2(r0.z, c0.z); red2(r0.w, c0.w);
        red2(r1.x, c1.x); red2(r1.y, c1.y); red2(r1.z, c1.z); red2(r1.w, c1.w);
    } else if (base < E) {
        for (int j = base; j < E; j++) red2(__ldcs(row + j), __ldcs(col + j));
    }
}

// ---------------------------------------------------------------------------
// Epilogue: h = tanh(dinv*sum + b3); out = h @ Wc + bc.
// d_out: out[N,16] then h[N,2].  Coalesced writes via smem staging.
// ---------------------------------------------------------------------------
__global__ void k_final(const float* __restrict__ Wc,
                        const float* __restrict__ b3,
                        const float* __restrict__ bc,
                        float* __restrict__ out, int n) {
    __shared__ float sh0[256];
    __shared__ float sh1[256];
    int node = blockIdx.x * 256 + threadIdx.x;
    float h0 = 0.f, h1 = 0.f;
    if (node < n) {
        float2 a = g_a2[node];
        float d = rsqrtf(g_dinv[node]);
        h0 = tanhf(a.x * d + __ldg(&b3[0]));
        h1 = tanhf(a.y * d + __ldg(&b3[1]));
        float2* hp = reinterpret_cast<float2*>(out + (size_t)16 * n);
        __stcs(hp + node, make_float2(h0, h1));
    }
    sh0[threadIdx.x] = h0;
    sh1[threadIdx.x] = h1;
    __syncthreads();

    int blockNodes = min(256, n - (int)blockIdx.x * 256);
    if (blockNodes <= 0) return;
    float4* o4 = reinterpret_cast<float4*>(out + (size_t)blockIdx.x * 256 * 16);
    for (int idx = threadIdx.x; idx < blockNodes * 4; idx += 256) {
        int nd = idx >> 2;
        int j  = (idx & 3) * 4;
        float H0 = sh0[nd], H1 = sh1[nd];
        float4 v;
        v.x = H0 * __ldg(&Wc[j + 0]) + H1 * __ldg(&Wc[16 + j + 0]) + __ldg(&bc[j + 0]);
        v.y = H0 * __ldg(&Wc[j + 1]) + H1 * __ldg(&Wc[16 + j + 1]) + __ldg(&bc[j + 1]);
        v.z = H0 * __ldg(&Wc[j + 2]) + H1 * __ldg(&Wc[16 + j + 2]) + __ldg(&bc[j + 2]);
        v.w = H0 * __ldg(&Wc[j + 3]) + H1 * __ldg(&Wc[16 + j + 3]) + __ldg(&bc[j + 3]);
        __stcs(o4 + idx, v);
    }
}

// ---------------------------------------------------------------------------
// Launch (sequential; overlap proven counterproductive on shared LTS cap)
// ---------------------------------------------------------------------------
extern "C" void kernel_launch(void* const* d_in, const int* in_sizes, int n_in,
                              void* d_out, int out_size) {
    const float* x  = (const float*)d_in[0];
    const int*   ei = (const int*)d_in[1];
    const float* W1 = (const float*)d_in[2];
    const float* b1 = (const float*)d_in[3];
    const float* W2 = (const float*)d_in[4];
    const float* b2 = (const float*)d_in[5];
    const float* W3 = (const float*)d_in[6];
    const float* b3 = (const float*)d_in[7];
    const float* Wc = (const float*)d_in[8];
    const float* bc = (const float*)d_in[9];
    float* out = (float*)d_out;

    const int n = in_sizes[0] / 128;
    const int E = in_sizes[1] / 2;
    const int* row = ei;       // source
    const int* col = ei + E;   // target

    const int TB = 256;
    int nodeBlocks = (n + TB - 1) / TB;
    int edgeBlocks = ((E + 7) / 8 + TB - 1) / TB;
    int projBlocks = 148 * 3;

    // degree
    k_init_deg<<<nodeBlocks, TB>>>(n);
    k_count_deg<<<edgeBlocks, TB>>>(col, E);

    // layer 1
    k_proj1<<<projBlocks, TB>>>(x, W1, n);
    k_scatter4<<<edgeBlocks, TB>>>(row, col, E);

    // layer 2
    k_proj2<<<nodeBlocks, TB>>>(W2, b1, n);
    k_scatter4<<<edgeBlocks, TB>>>(row, col, E);

    // layer 3
    k_proj3<<<nodeBlocks, TB>>>(W3, b2, n);
    k_scatter2<<<edgeBlocks, TB>>>(row, col, E);

    // classifier epilogue
    k_final<<<nodeBlocks, TB>>>(Wc, b3, bc, out, n);
}

// round 8
// speedup vs baseline: 1.6421x; 1.0746x over previous
#include <cuda_runtime.h>
#include <cstdint>

#define NMAX 1000000

// Scratch (__device__ globals; no allocation allowed)
__device__ float4 g_proj[NMAX];    // projd = proj * dinv   (layers 1,2)
__device__ float4 g_agg[NMAX];     // running sum (seeded with projd[self])
__device__ float  g_dinv[NMAX];    // holds DEGREE (consumers apply rsqrtf)
__device__ float2 g_p2[NMAX];      // layer-3 projd (2-wide)
__device__ float2 g_a2[NMAX];      // layer-3 sum

// ---------------------------------------------------------------------------
// degree
// ---------------------------------------------------------------------------
__global__ void k_init_deg(int n) {
    int i = blockIdx.x * blockDim.x + threadIdx.x;
    if (i < n) g_dinv[i] = 1.0f;  // self-loop
}

__device__ __forceinline__ void red_deg(int c) {
    asm volatile("red.global.add.f32 [%0], %1;" :: "l"(&g_dinv[c]), "f"(1.0f) : "memory");
}

__global__ void k_count_deg(const int* __restrict__ col, int E) {
    int t = blockIdx.x * blockDim.x + threadIdx.x;
    int base = t * 8;
    if (base + 8 <= E) {
        int4 c0 = __ldcs(reinterpret_cast<const int4*>(col + base));
        int4 c1 = __ldcs(reinterpret_cast<const int4*>(col + base) + 1);
        red_deg(c0.x); red_deg(c0.y); red_deg(c0.z); red_deg(c0.w);
        red_deg(c1.x); red_deg(c1.y); red_deg(c1.z); red_deg(c1.w);
    } else if (base < E) {
        for (int j = base; j < E; j++) red_deg(__ldcs(col + j));
    }
}

// ---------------------------------------------------------------------------
// Layer 1: projd = (x @ W1) * rsqrt(deg).  Warp handles 2 nodes/iter with
// software pipelining (next pair's 2x128B loads in flight during reduction).
// W in registers, 11-shuffle transpose reduction per node.
// Seeds agg = projd (self-loop term).
// ---------------------------------------------------------------------------
__global__ void __launch_bounds__(256, 5)
k_proj1(const float* __restrict__ x, const float* __restrict__ W1, int n) {
    int lane = threadIdx.x & 31;
    int warp = (blockIdx.x * blockDim.x + threadIdx.x) >> 5;
    int nwarps = (gridDim.x * blockDim.x) >> 5;

    const float4* W = reinterpret_cast<const float4*>(W1);  // W1 row k -> float4
    float4 w0 = W[4 * lane + 0];
    float4 w1 = W[4 * lane + 1];
    float4 w2 = W[4 * lane + 2];
    float4 w3 = W[4 * lane + 3];

    const float4* x4 = reinterpret_cast<const float4*>(x);
    const unsigned FULL = 0xffffffffu;
    const float4 Z = make_float4(0.f, 0.f, 0.f, 0.f);
    int npairs = (n + 1) >> 1;

    int pair = warp;
    if (pair >= npairs) return;

    // prologue loads
    int nodeA = pair * 2, nodeB = nodeA + 1;
    bool hasB = nodeB < n;
    float4 xa = __ldcs(x4 + (size_t)nodeA * 32 + lane);
    float4 xb = hasB ? __ldcs(x4 + (size_t)nodeB * 32 + lane) : Z;

    while (true) {
        // prefetch next pair (keeps 4 loads in flight per warp)
        int nextPair = pair + nwarps;
        float4 nxa = Z, nxb = Z;
        bool hasNext = nextPair < npairs;
        bool nHasB = false;
        if (hasNext) {
            int nA = nextPair * 2, nB = nA + 1;
            nHasB = nB < n;
            nxa = __ldcs(x4 + (size_t)nA * 32 + lane);
            nxb = nHasB ? __ldcs(x4 + (size_t)nB * 32 + lane) : Z;
        }

        float a0 = xa.x * w0.x + xa.y * w1.x + xa.z * w2.x + xa.w * w3.x;
        float a1 = xa.x * w0.y + xa.y * w1.y + xa.z * w2.y + xa.w * w3.y;
        float a2 = xa.x * w0.z + xa.y * w1.z + xa.z * w2.z + xa.w * w3.z;
        float a3 = xa.x * w0.w + xa.y * w1.w + xa.z * w2.w + xa.w * w3.w;
        float b0 = xb.x * w0.x + xb.y * w1.x + xb.z * w2.x + xb.w * w3.x;
        float b1 = xb.x * w0.y + xb.y * w1.y + xb.z * w2.y + xb.w * w3.y;
        float b2 = xb.x * w0.z + xb.y * w1.z + xb.z * w2.z + xb.w * w3.z;
        float b3 = xb.x * w0.w + xb.y * w1.w + xb.z * w2.w + xb.w * w3.w;

        a0 += __shfl_xor_sync(FULL, a0, 16); b0 += __shfl_xor_sync(FULL, b0, 16);
        a1 += __shfl_xor_sync(FULL, a1, 16); b1 += __shfl_xor_sync(FULL, b1, 16);
        a2 += __shfl_xor_sync(FULL, a2, 16); b2 += __shfl_xor_sync(FULL, b2, 16);
        a3 += __shfl_xor_sync(FULL, a3, 16); b3 += __shfl_xor_sync(FULL, b3, 16);
        a0 += __shfl_xor_sync(FULL, a0, 8);  b0 += __shfl_xor_sync(FULL, b0, 8);
        a1 += __shfl_xor_sync(FULL, a1, 8);  b1 += __shfl_xor_sync(FULL, b1, 8);
        a2 += __shfl_xor_sync(FULL, a2, 8);  b2 += __shfl_xor_sync(FULL, b2, 8);
        a3 += __shfl_xor_sync(FULL, a3, 8);  b3 += __shfl_xor_sync(FULL, b3, 8);

        // lane group g = lane>>3 owns output component g
        int g = lane >> 3;
        float va = (g == 0) ? a0 : (g == 1) ? a1 : (g == 2) ? a2 : a3;
        float vb = (g == 0) ? b0 : (g == 1) ? b1 : (g == 2) ? b2 : b3;
        va += __shfl_xor_sync(FULL, va, 4);  vb += __shfl_xor_sync(FULL, vb, 4);
        va += __shfl_xor_sync(FULL, va, 2);  vb += __shfl_xor_sync(FULL, vb, 2);
        va += __shfl_xor_sync(FULL, va, 1);  vb += __shfl_xor_sync(FULL, vb, 1);

        int sub = lane & 7;
        bool isA = (sub == 0);
        bool isB = (sub == 4) && hasB;
        if (isA | isB) {
            int nod  = isA ? nodeA : nodeB;
            float v  = isA ? va : vb;
            float d  = rsqrtf(__ldg(&g_dinv[nod]));
            float pv = v * d;
            reinterpret_cast<float*>(&g_proj[nod])[g] = pv;
            reinterpret_cast<float*>(&g_agg[nod])[g]  = pv;
        }

        if (!hasNext) break;
        pair = nextPair;
        nodeA = pair * 2; nodeB = nodeA + 1;
        hasB = nHasB;
        xa = nxa; xb = nxb;
    }
}

// ---------------------------------------------------------------------------
// Edge scatter (4-wide): sum[c] += projd[r].  8 edges/thread (measured best).
// ---------------------------------------------------------------------------
__device__ __forceinline__ void red4(int r, int c) {
    float4 p = __ldcg(&g_proj[r]);
    asm volatile("red.global.add.v4.f32 [%0], {%1,%2,%3,%4};"
                 :: "l"(&g_agg[c]), "f"(p.x), "f"(p.y), "f"(p.z), "f"(p.w)
                 : "memory");
}

__global__ void k_scatter4(const int* __restrict__ row,
                           const int* __restrict__ col, int E) {
    int t = blockIdx.x * blockDim.x + threadIdx.x;
    int base = t * 8;
    if (base + 8 <= E) {
        int4 r0 = __ldcs(reinterpret_cast<const int4*>(row + base));
        int4 r1 = __ldcs(reinterpret_cast<const int4*>(row + base) + 1);
        int4 c0 = __ldcs(reinterpret_cast<const int4*>(col + base));
        int4 c1 = __ldcs(reinterpret_cast<const int4*>(col + base) + 1);
        red4(r0.x, c0.x); red4(r0.y, c0.y); red4(r0.z, c0.z); red4(r0.w, c0.w);
        red4(r1.x, c1.x); red4(r1.y, c1.y); red4(r1.z, c1.z); red4(r1.w, c1.w);
    } else if (base < E) {
        for (int j = base; j < E; j++) red4(__ldcs(row + j), __ldcs(col + j));
    }
}

// ---------------------------------------------------------------------------
// Layer 2: t = tanh(dinv*sum + b1); projd = (t @ W2) * dinv; reseed sum.
// ---------------------------------------------------------------------------
__global__ void k_proj2(const float* __restrict__ W2,
                        const float* __restrict__ b1, int n) {
    int i = blockIdx.x * blockDim.x + threadIdx.x;
    if (i >= n) return;
    float4 a = g_agg[i];
    float d = rsqrtf(g_dinv[i]);
    float t0 = tanhf(a.x * d + __ldg(&b1[0]));
    float t1 = tanhf(a.y * d + __ldg(&b1[1]));
    float t2 = tanhf(a.z * d + __ldg(&b1[2]));
    float t3 = tanhf(a.w * d + __ldg(&b1[3]));
    float4 p;
    p.x = (t0 * __ldg(&W2[0]) + t1 * __ldg(&W2[4]) + t2 * __ldg(&W2[8])  + t3 * __ldg(&W2[12])) * d;
    p.y = (t0 * __ldg(&W2[1]) + t1 * __ldg(&W2[5]) + t2 * __ldg(&W2[9])  + t3 * __ldg(&W2[13])) * d;
    p.z = (t0 * __ldg(&W2[2]) + t1 * __ldg(&W2[6]) + t2 * __ldg(&W2[10]) + t3 * __ldg(&W2[14])) * d;
    p.w = (t0 * __ldg(&W2[3]) + t1 * __ldg(&W2[7]) + t2 * __ldg(&W2[11]) + t3 * __ldg(&W2[15])) * d;
    g_proj[i] = p;
    g_agg[i]  = p;
}

// ---------------------------------------------------------------------------
// Layer 3: t = tanh(dinv*sum + b2); projd2 = (t @ W3) * dinv (2-wide).
// ---------------------------------------------------------------------------
__global__ void k_proj3(const float* __restrict__ W3,
                        const float* __restrict__ b2, int n) {
    int i = blockIdx.x * blockDim.x + threadIdx.x;
    if (i >= n) return;
    float4 a = g_agg[i];
    float d = rsqrtf(g_dinv[i]);
    float t0 = tanhf(a.x * d + __ldg(&b2[0]));
    float t1 = tanhf(a.y * d + __ldg(&b2[1]));
    float t2 = tanhf(a.z * d + __ldg(&b2[2]));
    float t3 = tanhf(a.w * d + __ldg(&b2[3]));
    float p0 = (t0 * __ldg(&W3[0]) + t1 * __ldg(&W3[2]) + t2 * __ldg(&W3[4]) + t3 * __ldg(&W3[6])) * d;
    float p1 = (t0 * __ldg(&W3[1]) + t1 * __ldg(&W3[3]) + t2 * __ldg(&W3[5]) + t3 * __ldg(&W3[7])) * d;
    float2 pd = make_float2(p0, p1);
    g_p2[i] = pd;
    g_a2[i] = pd;
}

__device__ __forceinline__ void red2(int r, int c) {
    float2 p = __ldcg(&g_p2[r]);
    asm volatile("red.global.add.v2.f32 [%0], {%1,%2};"
                 :: "l"(&g_a2[c]), "f"(p.x), "f"(p.y)
                 : "memory");
}

__global__ void k_scatter2(const int* __restrict__ row,
                           const int* __restrict__ col, int E) {
    int t = blockIdx.x * blockDim.x + threadIdx.x;
    int base = t * 8;
    if (base + 8 <= E) {
        int4 r0 = __ldcs(reinterpret_cast<const int4*>(row + base));
        int4 r1 = __ldcs(reinterpret_cast<const int4*>(row + base) + 1);
        int4 c0 = __ldcs(reinterpret_cast<const int4*>(col + base));
        int4 c1 = __ldcs(reinterpret_cast<const int4*>(col + base) + 1);
        red2(r0.x, c0.x); red2(r0.y, c0.y); red2(r0.z, c0.z); red2(r0.w, c0.w);
        red2(r1.x, c1.x); red2(r1.y, c1.y); red2(r1.z, c1.z); red2(r1.w, c1.w);
    } else if (base < E) {
        for (int j = base; j < E; j++) red2(__ldcs(row + j), __ldcs(col + j));
    }
}

// ---------------------------------------------------------------------------
// Epilogue: h = tanh(dinv*sum + b3); out = h @ Wc + bc.
// d_out: out[N,16] then h[N,2].  Coalesced writes via smem staging.
// ---------------------------------------------------------------------------
__global__ void k_final(const float* __restrict__ Wc,
                        const float* __restrict__ b3,
                        const float* __restrict__ bc,
                        float* __restrict__ out, int n) {
    __shared__ float sh0[256];
    __shared__ float sh1[256];
    int node = blockIdx.x * 256 + threadIdx.x;
    float h0 = 0.f, h1 = 0.f;
    if (node < n) {
        float2 a = g_a2[node];
        float d = rsqrtf(g_dinv[node]);
        h0 = tanhf(a.x * d + __ldg(&b3[0]));
        h1 = tanhf(a.y * d + __ldg(&b3[1]));
        float2* hp = reinterpret_cast<float2*>(out + (size_t)16 * n);
        __stcs(hp + node, make_float2(h0, h1));
    }
    sh0[threadIdx.x] = h0;
    sh1[threadIdx.x] = h1;
    __syncthreads();

    int blockNodes = min(256, n - (int)blockIdx.x * 256);
    if (blockNodes <= 0) return;
    float4* o4 = reinterpret_cast<float4*>(out + (size_t)blockIdx.x * 256 * 16);
    for (int idx = threadIdx.x; idx < blockNodes * 4; idx += 256) {
        int nd = idx >> 2;
        int j  = (idx & 3) * 4;
        float H0 = sh0[nd], H1 = sh1[nd];
        float4 v;
        v.x = H0 * __ldg(&Wc[j + 0]) + H1 * __ldg(&Wc[16 + j + 0]) + __ldg(&bc[j + 0]);
        v.y = H0 * __ldg(&Wc[j + 1]) + H1 * __ldg(&Wc[16 + j + 1]) + __ldg(&bc[j + 1]);
        v.z = H0 * __ldg(&Wc[j + 2]) + H1 * __ldg(&Wc[16 + j + 2]) + __ldg(&bc[j + 2]);
        v.w = H0 * __ldg(&Wc[j + 3]) + H1 * __ldg(&Wc[16 + j + 3]) + __ldg(&bc[j + 3]);
        __stcs(o4 + idx, v);
    }
}

// ---------------------------------------------------------------------------
// Launch
// ---------------------------------------------------------------------------
extern "C" void kernel_launch(void* const* d_in, const int* in_sizes, int n_in,
                              void* d_out, int out_size) {
    const float* x  = (const float*)d_in[0];
    const int*   ei = (const int*)d_in[1];
    const float* W1 = (const float*)d_in[2];
    const float* b1 = (const float*)d_in[3];
    const float* W2 = (const float*)d_in[4];
    const float* b2 = (const float*)d_in[5];
    const float* W3 = (const float*)d_in[6];
    const float* b3 = (const float*)d_in[7];
    const float* Wc = (const float*)d_in[8];
    const float* bc = (const float*)d_in[9];
    float* out = (float*)d_out;

    const int n = in_sizes[0] / 128;
    const int E = in_sizes[1] / 2;
    const int* row = ei;       // source
    const int* col = ei + E;   // target

    const int TB = 256;
    int nodeBlocks = (n + TB - 1) / TB;
    int edgeBlocks = ((E + 7) / 8 + TB - 1) / TB;
    int projBlocks = 148 * 5;

    // degree
    k_init_deg<<<nodeBlocks, TB>>>(n);
    k_count_deg<<<edgeBlocks, TB>>>(col, E);

    // layer 1
    k_proj1<<<projBlocks, TB>>>(x, W1, n);
    k_scatter4<<<edgeBlocks, TB>>>(row, col, E);

    // layer 2
    k_proj2<<<nodeBlocks, TB>>>(W2, b1, n);
    k_scatter4<<<edgeBlocks, TB>>>(row, col, E);

    // layer 3
    k_proj3<<<nodeBlocks, TB>>>(W3, b2, n);
    k_scatter2<<<edgeBlocks, TB>>>(row, col, E);

    // classifier epilogue
    k_final<<<nodeBlocks, TB>>>(Wc, b3, bc, out, n);
}